// round 9
// baseline (speedup 1.0000x reference)
#include <cuda_runtime.h>
#include <cstdint>

#define N_NODES 50000
#define N_EDGES 600000
#define N_TOT   (N_NODES + N_EDGES)
#define N_GRAPHS 256
#define D 128
#define NLAYER 4
#define BN_EPS 1e-5f

// ---------------- scratch (device globals; zero-initialized at load) ----------------
__device__ float g_h0[(size_t)N_NODES * D];      // ping buffer (atom emb, z of odd layers' input)
__device__ float g_h1[(size_t)N_NODES * D];      // pong buffer
__device__ float g_Wt4[NLAYER * D * D];          // per-layer W^T [k][n], tf32-rounded
__device__ float g_ct4[NLAYER * 243 * D];        // per-layer combo bond-embedding tables
__device__ float g_stats4[NLAYER * 2 * D];       // per-layer col sums + sumsq of z
__device__ float g_pool[N_GRAPHS * D];
__device__ int   g_off[N_NODES + 1];             // MUST be zero on kernel_launch entry
__device__ int   g_cur[N_NODES];
__device__ int   g_adj[N_TOT];                   // packed: src | (combo<<16)

__device__ __forceinline__ float tf32r(float x) {
    float y;
    asm("cvt.rna.tf32.f32 %0, %1;" : "=f"(y) : "f"(x));
    return y;
}

__device__ __forceinline__ void mma_tf32(float* c, const uint32_t* a, const uint32_t* b) {
    asm volatile(
        "mma.sync.aligned.m16n8k8.row.col.f32.tf32.tf32.f32 "
        "{%0,%1,%2,%3}, {%4,%5,%6,%7}, {%8,%9}, {%0,%1,%2,%3};"
        : "+f"(c[0]), "+f"(c[1]), "+f"(c[2]), "+f"(c[3])
        : "r"(a[0]), "r"(a[1]), "r"(a[2]), "r"(a[3]), "r"(b[0]), "r"(b[1]));
}

// =============== 1. atom embedding + degree histogram + stats zero ===============
__global__ void k_atomhist(const int* __restrict__ x, const float* __restrict__ aemb,
                           const int* __restrict__ e_dst) {
    int gid = blockIdx.x * blockDim.x + threadIdx.x;   // 1.6M threads
    int node = gid >> 5, lane = gid & 31;
    if (node < N_NODES) {
        const int* xi = x + (size_t)node * 9;
        float4 acc = make_float4(0.f, 0.f, 0.f, 0.f);
#pragma unroll
        for (int f = 0; f < 9; f++) {
            int v = __ldg(&xi[f]);
            float4 e = __ldg(&((const float4*)aemb)[(size_t)(f * 120 + v) * 32 + lane]);
            acc.x += e.x; acc.y += e.y; acc.z += e.z; acc.w += e.w;
        }
        ((float4*)g_h0)[(size_t)node * 32 + lane] = acc;
    }
    if (gid < N_EDGES) atomicAdd(&g_off[__ldg(&e_dst[gid])], 1);
    if (gid < NLAYER * 2 * D) g_stats4[gid] = 0.f;
}

// =============== 2. single-block scan (block 0) + all-layer prep (other blocks) ===============
#define CT_BLOCKS ((NLAYER * 243 + 7) / 8)            /* 122 */
#define WT_BLOCKS (NLAYER * D * D / 1024)             /* 64 */
__global__ void k_scanprep(const float* __restrict__ bemb, const float* __restrict__ W) {
    int b = blockIdx.x, t = threadIdx.x;              // 1024 threads
    if (b == 0) {
        __shared__ int sh[1024];
        int base = t * 49;
        int sum = 0;
        for (int i = 0; i < 49; i++) {
            int idx = base + i;
            if (idx < N_NODES) sum += g_off[idx] + 1;  // +1 self loop
        }
        sh[t] = sum;
        __syncthreads();
        for (int off = 1; off < 1024; off <<= 1) {
            int xv = (t >= off) ? sh[t - off] : 0;
            __syncthreads();
            sh[t] += xv;
            __syncthreads();
        }
        int run = sh[t] - sum;                         // exclusive start
        for (int i = 0; i < 49; i++) {
            int idx = base + i;
            if (idx < N_NODES) {
                int c = g_off[idx] + 1;
                g_off[idx] = run;
                g_cur[idx] = run;
                run += c;
            }
        }
        if (t == 1023) g_off[N_NODES] = run;           // == N_TOT
    } else if (b <= CT_BLOCKS) {
        int r = (b - 1) * 8 + (t >> 7);                // 0..971 = l*243 + combo
        int lane = t & 127;
        if (r < NLAYER * 243) {
            int l = r / 243, c = r % 243;
            const float* bl = bemb + (size_t)l * 5 * 7 * D;
            int cc = c;
            float acc = 0.f;
#pragma unroll
            for (int f = 0; f < 5; f++) {
                int dig = cc % 3; cc /= 3;
                acc += __ldg(&bl[(f * 7 + dig) * D + lane]);
            }
            g_ct4[(size_t)r * D + lane] = acc;
        }
    } else {
        int e = (b - 1 - CT_BLOCKS) * 1024 + t;        // 0..65535
        int l = e >> 14, idx = e & 16383;
        int k = idx >> 7, n = idx & 127;
        g_Wt4[e] = tf32r(__ldg(&W[(size_t)l * D * D + n * D + k]));
    }
}

// =============== 3. scatter edges into CSR ===============
__global__ void k_scatter(const int* __restrict__ e_src, const int* __restrict__ e_dst,
                          const int* __restrict__ ea) {
    int t = blockIdx.x * blockDim.x + threadIdx.x;
    if (t >= N_TOT) return;
    int d, s, comb;
    if (t < N_EDGES) {
        s = __ldg(&e_src[t]);
        d = __ldg(&e_dst[t]);
        const int* a = ea + (size_t)t * 5;
        comb = a[0] + 3 * a[1] + 9 * a[2] + 27 * a[3] + 81 * a[4];
    } else {
        d = s = t - N_EDGES;
        comb = 0;
    }
    int pos = atomicAdd(&g_cur[d], 1);
    g_adj[pos] = s | (comb << 16);
}

// =============== 4. fused layer: gather(+BN+ReLU) -> smem A -> tf32 MMA -> z + stats ======
// DOUBLE-BUFFERED: reads h from one buffer, writes z to the other (no cross-block hazard).
#define SA 132
#define SB 136
#define AS_FLOATS (64 * SA)
#define BS_FLOATS (128 * SB)
#define LAYER_SMEM ((AS_FLOATS + BS_FLOATS) * 4)   /* ~101KB -> 2 CTAs/SM */
#define LAYER_BLOCKS ((N_NODES + 63) / 64)         /* 782 */

__global__ __launch_bounds__(256, 2) void k_layer(int l, const float* __restrict__ bn_g,
                                                  const float* __restrict__ bn_b) {
    extern __shared__ float smem[];
    float* As = smem;                                 // [64][132]
    float* Bs = smem + AS_FLOATS;                     // [128][136]
    const uint32_t* Asu = (const uint32_t*)As;
    const uint32_t* Bsu = (const uint32_t*)Bs;

    // ping-pong: even layers read g_h0 / write g_h1; odd layers the reverse
    const float4* h4 = (l & 1) ? (const float4*)g_h1 : (const float4*)g_h0;
    float* hout = (l & 1) ? g_h0 : g_h1;

    int t = threadIdx.x;
    int wid = t >> 5, lane = t & 31;
    int row0 = blockIdx.x * 64;

    // ---- kick off B tile load (overlaps with gather below) ----
    const float4* B4 = (const float4*)(g_Wt4 + (size_t)l * D * D);
#pragma unroll
    for (int i = 0; i < 16; i++) {
        int idx = t + i * 256;
        int r = idx >> 5, q = idx & 31;
        *(float4*)&Bs[r * SB + q * 4] = __ldg(&B4[idx]);
    }

    // ---- BN constants for this thread's 4 columns (lane*4 .. +3) ----
    float scx, scy, scz, scw, shx, shy, shz, shw, flo;
    if (l > 0) {
        flo = 0.f;
        const float* st = g_stats4 + (l - 1) * 256;
        const float* gg = bn_g + (l - 1) * D;
        const float* bb = bn_b + (l - 1) * D;
        int c0 = lane * 4;
        float sc[4], sh[4];
#pragma unroll
        for (int j = 0; j < 4; j++) {
            float s = __ldg(&st[c0 + j]);
            float q = __ldg(&st[128 + c0 + j]);
            float mu = s * (1.f / (float)N_NODES);
            float var = q * (1.f / (float)N_NODES) - mu * mu;
            float rstd = rsqrtf(fmaxf(var, 0.f) + BN_EPS);
            sc[j] = rstd * __ldg(&gg[c0 + j]);
            sh[j] = __ldg(&bb[c0 + j]) - mu * sc[j];
        }
        scx = sc[0]; scy = sc[1]; scz = sc[2]; scw = sc[3];
        shx = sh[0]; shy = sh[1]; shz = sh[2]; shw = sh[3];
    } else {
        scx = scy = scz = scw = 1.f;
        shx = shy = shz = shw = 0.f;
        flo = __int_as_float(0xff800000);   // -inf: identity on h0
    }

    // ---- gather: warp wid aggregates nodes row0 + wid*8 .. +7 into As ----
    const float4* ct4 = (const float4*)(g_ct4 + (size_t)l * 243 * D);
#pragma unroll 1
    for (int i = 0; i < 8; i++) {
        int r = wid * 8 + i;
        int node = row0 + r;
        float4 acc = make_float4(0.f, 0.f, 0.f, 0.f);
        if (node < N_NODES) {
            int s = __ldg(&g_off[node]), e = __ldg(&g_off[node + 1]);
            int j = s;
            for (; j + 4 <= e; j += 4) {
                int p0 = __ldg(&g_adj[j]);
                int p1 = __ldg(&g_adj[j + 1]);
                int p2 = __ldg(&g_adj[j + 2]);
                int p3 = __ldg(&g_adj[j + 3]);
                float4 z0 = __ldcg(&h4[(size_t)(p0 & 0xFFFF) * 32 + lane]);
                float4 z1 = __ldcg(&h4[(size_t)(p1 & 0xFFFF) * 32 + lane]);
                float4 z2 = __ldcg(&h4[(size_t)(p2 & 0xFFFF) * 32 + lane]);
                float4 z3 = __ldcg(&h4[(size_t)(p3 & 0xFFFF) * 32 + lane]);
                float4 c0 = __ldg(&ct4[(p0 >> 16) * 32 + lane]);
                float4 c1 = __ldg(&ct4[(p1 >> 16) * 32 + lane]);
                float4 c2 = __ldg(&ct4[(p2 >> 16) * 32 + lane]);
                float4 c3 = __ldg(&ct4[(p3 >> 16) * 32 + lane]);
                acc.x += fmaxf(z0.x * scx + shx, flo) + c0.x;
                acc.y += fmaxf(z0.y * scy + shy, flo) + c0.y;
                acc.z += fmaxf(z0.z * scz + shz, flo) + c0.z;
                acc.w += fmaxf(z0.w * scw + shw, flo) + c0.w;
                acc.x += fmaxf(z1.x * scx + shx, flo) + c1.x;
                acc.y += fmaxf(z1.y * scy + shy, flo) + c1.y;
                acc.z += fmaxf(z1.z * scz + shz, flo) + c1.z;
                acc.w += fmaxf(z1.w * scw + shw, flo) + c1.w;
                acc.x += fmaxf(z2.x * scx + shx, flo) + c2.x;
                acc.y += fmaxf(z2.y * scy + shy, flo) + c2.y;
                acc.z += fmaxf(z2.z * scz + shz, flo) + c2.z;
                acc.w += fmaxf(z2.w * scw + shw, flo) + c2.w;
                acc.x += fmaxf(z3.x * scx + shx, flo) + c3.x;
                acc.y += fmaxf(z3.y * scy + shy, flo) + c3.y;
                acc.z += fmaxf(z3.z * scz + shz, flo) + c3.z;
                acc.w += fmaxf(z3.w * scw + shw, flo) + c3.w;
            }
            for (; j < e; j++) {
                int p = __ldg(&g_adj[j]);
                float4 z = __ldcg(&h4[(size_t)(p & 0xFFFF) * 32 + lane]);
                float4 c = __ldg(&ct4[(p >> 16) * 32 + lane]);
                acc.x += fmaxf(z.x * scx + shx, flo) + c.x;
                acc.y += fmaxf(z.y * scy + shy, flo) + c.y;
                acc.z += fmaxf(z.z * scz + shz, flo) + c.z;
                acc.w += fmaxf(z.w * scw + shw, flo) + c.w;
            }
        }
        acc.x = tf32r(acc.x); acc.y = tf32r(acc.y);
        acc.z = tf32r(acc.z); acc.w = tf32r(acc.w);
        *(float4*)&As[r * SA + lane * 4] = acc;
    }
    __syncthreads();

    // ---- MMA: 4x2 warp grid, each warp 16 rows x 64 cols ----
    int warpM = wid & 3, warpN = wid >> 2;
    float c[8][4];
#pragma unroll
    for (int nt = 0; nt < 8; nt++)
#pragma unroll
        for (int j = 0; j < 4; j++) c[nt][j] = 0.f;

    int lr = lane >> 2, lc = lane & 3;
#pragma unroll
    for (int kk = 0; kk < 16; kk++) {
        int k0 = kk * 8;
        uint32_t a[4], b[8][2];
        int r = warpM * 16 + lr;
        a[0] = Asu[r * SA + k0 + lc];
        a[1] = Asu[(r + 8) * SA + k0 + lc];
        a[2] = Asu[r * SA + k0 + 4 + lc];
        a[3] = Asu[(r + 8) * SA + k0 + 4 + lc];
#pragma unroll
        for (int nt = 0; nt < 8; nt++) {
            int n = warpN * 64 + nt * 8 + lr;
            b[nt][0] = Bsu[(k0 + lc) * SB + n];
            b[nt][1] = Bsu[(k0 + 4 + lc) * SB + n];
        }
#pragma unroll
        for (int nt = 0; nt < 8; nt++)
            mma_tf32(c[nt], a, b[nt]);
    }

    // ---- store z + stats (shfl reduce over lr, then global atomics from lanes 0-3) ----
    int r0 = row0 + warpM * 16 + lr;
    bool rok0 = (r0 < N_NODES), rok1 = (r0 + 8 < N_NODES);
#pragma unroll
    for (int nt = 0; nt < 8; nt++) {
        int col = warpN * 64 + nt * 8 + lc * 2;
        if (rok0)
            *(float2*)&hout[(size_t)r0 * D + col] = make_float2(c[nt][0], c[nt][1]);
        if (rok1)
            *(float2*)&hout[(size_t)(r0 + 8) * D + col] = make_float2(c[nt][2], c[nt][3]);
    }
    float* stat = g_stats4 + l * 256;
#pragma unroll
    for (int nt = 0; nt < 8; nt++) {
#pragma unroll
        for (int jj = 0; jj < 2; jj++) {
            float v0 = rok0 ? c[nt][jj] : 0.f;
            float v1 = rok1 ? c[nt][jj + 2] : 0.f;
            float s = v0 + v1;
            float q = v0 * v0 + v1 * v1;
            s += __shfl_down_sync(0xFFFFFFFFu, s, 16);
            q += __shfl_down_sync(0xFFFFFFFFu, q, 16);
            s += __shfl_down_sync(0xFFFFFFFFu, s, 8);
            q += __shfl_down_sync(0xFFFFFFFFu, q, 8);
            s += __shfl_down_sync(0xFFFFFFFFu, s, 4);
            q += __shfl_down_sync(0xFFFFFFFFu, q, 4);
            if (lane < 4) {
                int col = warpN * 64 + nt * 8 + lane * 2 + jj;
                atomicAdd(&stat[col], s);
                atomicAdd(&stat[128 + col], q);
            }
        }
    }
}

// =============== 5. pool: bounds bsearch + final BN + ReLU + mean ===============
// After 4 layers (even count), final z lives in g_h0.
__global__ void k_pool(const int* __restrict__ batch, const float* __restrict__ bn_g,
                       const float* __restrict__ bn_b) {
    int g = blockIdx.x, t = threadIdx.x;   // 128 threads
    int lo = 0, hi = N_NODES;
    while (lo < hi) { int m = (lo + hi) >> 1; if (__ldg(&batch[m]) < g) lo = m + 1; else hi = m; }
    int lo2 = lo, hi2 = N_NODES;
    while (lo2 < hi2) { int m = (lo2 + hi2) >> 1; if (__ldg(&batch[m]) < g + 1) lo2 = m + 1; else hi2 = m; }

    float s0 = g_stats4[3 * 256 + t];
    float q0 = g_stats4[3 * 256 + 128 + t];
    float mu = s0 / (float)N_NODES;
    float var = q0 / (float)N_NODES - mu * mu;
    float rstd = rsqrtf(fmaxf(var, 0.f) + BN_EPS);
    float sc = rstd * __ldg(&bn_g[3 * D + t]);
    float sh = __ldg(&bn_b[3 * D + t]) - mu * sc;

    float s = 0.f;
    for (int r = lo; r < lo2; r++) {
        float v = g_h0[(size_t)r * D + t];
        s += fmaxf(v * sc + sh, 0.f);
    }
    int cnt = lo2 - lo;
    g_pool[g * D + t] = s / (float)max(cnt, 1);
}

// =============== 6. MLP head + g_off re-zero for next call ===============
__global__ void k_mlp(const float* __restrict__ w1, const float* __restrict__ b1,
                      const float* __restrict__ w2, const float* __restrict__ b2,
                      float* __restrict__ out) {
    int g = blockIdx.x, j = threadIdx.x;   // 64 threads
    const float* gp = g_pool + g * D;
    const float* wr = w1 + j * D;
    float a = b1[j];
#pragma unroll 4
    for (int k = 0; k < D; k++) a += gp[k] * wr[k];
    a = fmaxf(a, 0.f);
    float v = a * w2[j];
#pragma unroll
    for (int o = 16; o > 0; o >>= 1) v += __shfl_down_sync(0xFFFFFFFFu, v, o);
    __shared__ float sh[2];
    if ((j & 31) == 0) sh[j >> 5] = v;
    __syncthreads();
    if (j == 0) out[g] = sh[0] + sh[1] + b2[0];
    // maintain invariant: g_off zeroed for the next kernel_launch call
    for (int i = g * 64 + j; i < N_NODES + 1; i += N_GRAPHS * 64) g_off[i] = 0;
}

// ---------------- launch ----------------
extern "C" void kernel_launch(void* const* d_in, const int* in_sizes, int n_in,
                              void* d_out, int out_size) {
    const int*   x        = (const int*)d_in[0];
    const int*   ei       = (const int*)d_in[1];
    const int*   ea       = (const int*)d_in[2];
    const int*   batch    = (const int*)d_in[3];
    const float* atom_emb = (const float*)d_in[4];
    const float* bond_emb = (const float*)d_in[5];
    const float* lin_w    = (const float*)d_in[6];
    const float* bn_g     = (const float*)d_in[8];
    const float* bn_b     = (const float*)d_in[9];
    const float* w1       = (const float*)d_in[10];
    const float* b1       = (const float*)d_in[11];
    const float* w2       = (const float*)d_in[12];
    const float* b2       = (const float*)d_in[13];
    float* out = (float*)d_out;

    const int* e_src = ei;
    const int* e_dst = ei + N_EDGES;

    cudaFuncSetAttribute(k_layer, cudaFuncAttributeMaxDynamicSharedMemorySize, LAYER_SMEM);

    k_atomhist<<<(N_NODES * 32 + 255) / 256, 256>>>(x, atom_emb, e_dst);
    k_scanprep<<<1 + CT_BLOCKS + WT_BLOCKS, 1024>>>(bond_emb, lin_w);
    k_scatter<<<(N_TOT + 255) / 256, 256>>>(e_src, e_dst, ea);

    for (int l = 0; l < NLAYER; l++)
        k_layer<<<LAYER_BLOCKS, 256, LAYER_SMEM>>>(l, bn_g, bn_b);

    k_pool<<<N_GRAPHS, D>>>(batch, bn_g, bn_b);
    k_mlp<<<N_GRAPHS, 64>>>(w1, b1, w2, b2, out);
}

// round 10
// speedup vs baseline: 1.0073x; 1.0073x over previous
#include <cuda_runtime.h>
#include <cstdint>

#define N_NODES 50000
#define N_EDGES 600000
#define N_TOT   (N_NODES + N_EDGES)
#define N_GRAPHS 256
#define D 128
#define NLAYER 4
#define BN_EPS 1e-5f

// ---------------- scratch (device globals; zero-initialized at load) ----------------
__device__ float g_h0[(size_t)N_NODES * D];      // h buffer (atom emb / z ping)
__device__ float g_h1[(size_t)N_NODES * D];      // aggr buffer / z pong
__device__ float g_Wt4[NLAYER * D * D];          // per-layer W^T [k][n], tf32-rounded
__device__ float g_ct4[NLAYER * 243 * D];        // per-layer combo bond-embedding tables
__device__ float g_stats4[NLAYER * 2 * D];       // per-layer col sums + sumsq of z
__device__ float g_pool[N_GRAPHS * D];           // zeroed each call in k_atomhist
__device__ int   g_off[N_NODES + 1];             // MUST be zero on kernel_launch entry
__device__ int   g_cur[N_NODES];
__device__ int   g_adj[N_TOT];                   // packed: src | (combo<<16)

__device__ __forceinline__ float tf32r(float x) {
    float y;
    asm("cvt.rna.tf32.f32 %0, %1;" : "=f"(y) : "f"(x));
    return y;
}

__device__ __forceinline__ void mma_tf32(float* c, const uint32_t* a, const uint32_t* b) {
    asm volatile(
        "mma.sync.aligned.m16n8k8.row.col.f32.tf32.tf32.f32 "
        "{%0,%1,%2,%3}, {%4,%5,%6,%7}, {%8,%9}, {%0,%1,%2,%3};"
        : "+f"(c[0]), "+f"(c[1]), "+f"(c[2]), "+f"(c[3])
        : "r"(a[0]), "r"(a[1]), "r"(a[2]), "r"(a[3]), "r"(b[0]), "r"(b[1]));
}

// =============== 1. atom embedding + degree histogram + zero stats/pool ===============
__global__ void k_atomhist(const int* __restrict__ x, const float* __restrict__ aemb,
                           const int* __restrict__ e_dst) {
    int gid = blockIdx.x * blockDim.x + threadIdx.x;   // 1.6M threads
    int node = gid >> 5, lane = gid & 31;
    if (node < N_NODES) {
        const int* xi = x + (size_t)node * 9;
        float4 acc = make_float4(0.f, 0.f, 0.f, 0.f);
#pragma unroll
        for (int f = 0; f < 9; f++) {
            int v = __ldg(&xi[f]);
            float4 e = __ldg(&((const float4*)aemb)[(size_t)(f * 120 + v) * 32 + lane]);
            acc.x += e.x; acc.y += e.y; acc.z += e.z; acc.w += e.w;
        }
        ((float4*)g_h0)[(size_t)node * 32 + lane] = acc;
    }
    if (gid < N_EDGES) atomicAdd(&g_off[__ldg(&e_dst[gid])], 1);
    if (gid < NLAYER * 2 * D) g_stats4[gid] = 0.f;
    if (gid < N_GRAPHS * D) g_pool[gid] = 0.f;
}

// =============== 2. single-block scan (block 0) + all-layer prep (other blocks) ===============
#define CT_BLOCKS ((NLAYER * 243 + 7) / 8)            /* 122 */
#define WT_BLOCKS (NLAYER * D * D / 1024)             /* 64 */
__global__ void k_scanprep(const float* __restrict__ bemb, const float* __restrict__ W) {
    int b = blockIdx.x, t = threadIdx.x;              // 1024 threads
    if (b == 0) {
        __shared__ int sh[1024];
        int base = t * 49;
        int sum = 0;
        for (int i = 0; i < 49; i++) {
            int idx = base + i;
            if (idx < N_NODES) sum += g_off[idx] + 1;  // +1 self loop
        }
        sh[t] = sum;
        __syncthreads();
        for (int off = 1; off < 1024; off <<= 1) {
            int xv = (t >= off) ? sh[t - off] : 0;
            __syncthreads();
            sh[t] += xv;
            __syncthreads();
        }
        int run = sh[t] - sum;                         // exclusive start
        for (int i = 0; i < 49; i++) {
            int idx = base + i;
            if (idx < N_NODES) {
                int c = g_off[idx] + 1;
                g_off[idx] = run;
                g_cur[idx] = run;
                run += c;
            }
        }
        if (t == 1023) g_off[N_NODES] = run;           // == N_TOT
    } else if (b <= CT_BLOCKS) {
        int r = (b - 1) * 8 + (t >> 7);                // 0..971 = l*243 + combo
        int lane = t & 127;
        if (r < NLAYER * 243) {
            int l = r / 243, c = r % 243;
            const float* bl = bemb + (size_t)l * 5 * 7 * D;
            int cc = c;
            float acc = 0.f;
#pragma unroll
            for (int f = 0; f < 5; f++) {
                int dig = cc % 3; cc /= 3;
                acc += __ldg(&bl[(f * 7 + dig) * D + lane]);
            }
            g_ct4[(size_t)r * D + lane] = acc;
        }
    } else {
        int e = (b - 1 - CT_BLOCKS) * 1024 + t;        // 0..65535
        int l = e >> 14, idx = e & 16383;
        int k = idx >> 7, n = idx & 127;
        g_Wt4[e] = tf32r(__ldg(&W[(size_t)l * D * D + n * D + k]));
    }
}

// =============== 3. scatter edges into CSR ===============
__global__ void k_scatter(const int* __restrict__ e_src, const int* __restrict__ e_dst,
                          const int* __restrict__ ea) {
    int t = blockIdx.x * blockDim.x + threadIdx.x;
    if (t >= N_TOT) return;
    int d, s, comb;
    if (t < N_EDGES) {
        s = __ldg(&e_src[t]);
        d = __ldg(&e_dst[t]);
        const int* a = ea + (size_t)t * 5;
        comb = a[0] + 3 * a[1] + 9 * a[2] + 27 * a[3] + 81 * a[4];
    } else {
        d = s = t - N_EDGES;
        comb = 0;
    }
    int pos = atomicAdd(&g_cur[d], 1);
    g_adj[pos] = s | (comb << 16);
}

// =============== 4. aggregation: warp-per-node, no smem (measured 39.7us, occ 58%) ========
// reads g_h0, writes g_h1 (tf32-rounded aggregate incl. fused BN+ReLU of prev layer)
__global__ __launch_bounds__(256) void k_aggr(int l, const float* __restrict__ bn_g,
                                              const float* __restrict__ bn_b) {
    int gid = blockIdx.x * blockDim.x + threadIdx.x;
    int node = gid >> 5, lane = gid & 31;
    if (node >= N_NODES) return;

    float scx, scy, scz, scw, shx, shy, shz, shw, flo;
    if (l > 0) {
        flo = 0.f;
        const float* st = g_stats4 + (l - 1) * 256;
        const float* gg = bn_g + (l - 1) * D;
        const float* bb = bn_b + (l - 1) * D;
        int c0 = lane * 4;
        float sc[4], sh[4];
#pragma unroll
        for (int j = 0; j < 4; j++) {
            float s = __ldg(&st[c0 + j]);
            float q = __ldg(&st[128 + c0 + j]);
            float mu = s * (1.f / (float)N_NODES);
            float var = q * (1.f / (float)N_NODES) - mu * mu;
            float rstd = rsqrtf(fmaxf(var, 0.f) + BN_EPS);
            sc[j] = rstd * __ldg(&gg[c0 + j]);
            sh[j] = __ldg(&bb[c0 + j]) - mu * sc[j];
        }
        scx = sc[0]; scy = sc[1]; scz = sc[2]; scw = sc[3];
        shx = sh[0]; shy = sh[1]; shz = sh[2]; shw = sh[3];
    } else {
        scx = scy = scz = scw = 1.f;
        shx = shy = shz = shw = 0.f;
        flo = __int_as_float(0xff800000);   // -inf: identity on h0
    }

    const float4* h4 = (const float4*)g_h0;
    const float4* ct4 = (const float4*)(g_ct4 + (size_t)l * 243 * D);
    int s = __ldg(&g_off[node]), e = __ldg(&g_off[node + 1]);
    float4 acc = make_float4(0.f, 0.f, 0.f, 0.f);
    int j = s;
    for (; j + 4 <= e; j += 4) {
        int p0 = __ldg(&g_adj[j]);
        int p1 = __ldg(&g_adj[j + 1]);
        int p2 = __ldg(&g_adj[j + 2]);
        int p3 = __ldg(&g_adj[j + 3]);
        float4 z0 = __ldcg(&h4[(size_t)(p0 & 0xFFFF) * 32 + lane]);
        float4 z1 = __ldcg(&h4[(size_t)(p1 & 0xFFFF) * 32 + lane]);
        float4 z2 = __ldcg(&h4[(size_t)(p2 & 0xFFFF) * 32 + lane]);
        float4 z3 = __ldcg(&h4[(size_t)(p3 & 0xFFFF) * 32 + lane]);
        float4 c0 = __ldg(&ct4[(p0 >> 16) * 32 + lane]);
        float4 c1 = __ldg(&ct4[(p1 >> 16) * 32 + lane]);
        float4 c2 = __ldg(&ct4[(p2 >> 16) * 32 + lane]);
        float4 c3 = __ldg(&ct4[(p3 >> 16) * 32 + lane]);
        acc.x += fmaxf(z0.x * scx + shx, flo) + c0.x;
        acc.y += fmaxf(z0.y * scy + shy, flo) + c0.y;
        acc.z += fmaxf(z0.z * scz + shz, flo) + c0.z;
        acc.w += fmaxf(z0.w * scw + shw, flo) + c0.w;
        acc.x += fmaxf(z1.x * scx + shx, flo) + c1.x;
        acc.y += fmaxf(z1.y * scy + shy, flo) + c1.y;
        acc.z += fmaxf(z1.z * scz + shz, flo) + c1.z;
        acc.w += fmaxf(z1.w * scw + shw, flo) + c1.w;
        acc.x += fmaxf(z2.x * scx + shx, flo) + c2.x;
        acc.y += fmaxf(z2.y * scy + shy, flo) + c2.y;
        acc.z += fmaxf(z2.z * scz + shz, flo) + c2.z;
        acc.w += fmaxf(z2.w * scw + shw, flo) + c2.w;
        acc.x += fmaxf(z3.x * scx + shx, flo) + c3.x;
        acc.y += fmaxf(z3.y * scy + shy, flo) + c3.y;
        acc.z += fmaxf(z3.z * scz + shz, flo) + c3.z;
        acc.w += fmaxf(z3.w * scw + shw, flo) + c3.w;
    }
    for (; j < e; j++) {
        int p = __ldg(&g_adj[j]);
        float4 z = __ldcg(&h4[(size_t)(p & 0xFFFF) * 32 + lane]);
        float4 c = __ldg(&ct4[(p >> 16) * 32 + lane]);
        acc.x += fmaxf(z.x * scx + shx, flo) + c.x;
        acc.y += fmaxf(z.y * scy + shy, flo) + c.y;
        acc.z += fmaxf(z.z * scz + shz, flo) + c.z;
        acc.w += fmaxf(z.w * scw + shw, flo) + c.w;
    }
    acc.x = tf32r(acc.x); acc.y = tf32r(acc.y);
    acc.z = tf32r(acc.z); acc.w = tf32r(acc.w);
    ((float4*)g_h1)[(size_t)node * 32 + lane] = acc;
}

// =============== 5. tf32 mma GEMM: z = aggr @ W^T; stats via shfl + global atomics =========
// reads g_h1 (aggr), writes z to g_h0. No smem atomics.
#define SA 132
#define SB 136
#define AS_FLOATS (64 * SA)
#define BS_FLOATS (128 * SB)
#define GEMM_SMEM ((AS_FLOATS + BS_FLOATS) * 4)    /* ~101KB -> 2 CTAs/SM */
#define GEMM_BLOCKS ((N_NODES + 63) / 64)          /* 782 */

__global__ __launch_bounds__(256, 2) void k_gemm(int l) {
    extern __shared__ float smem[];
    float* As = smem;                                 // [64][132]
    float* Bs = smem + AS_FLOATS;                     // [128][136]
    const uint32_t* Asu = (const uint32_t*)As;
    const uint32_t* Bsu = (const uint32_t*)Bs;

    int t = threadIdx.x;
    int wid = t >> 5, lane = t & 31;
    int warpM = wid & 3, warpN = wid >> 2;            // 4 x 2 warps: 16 rows x 64 cols each
    int row0 = blockIdx.x * 64;

    const float4* A4 = (const float4*)g_h1;
    const float4* B4 = (const float4*)(g_Wt4 + (size_t)l * D * D);
#pragma unroll
    for (int i = 0; i < 8; i++) {                     // A: 64 rows x 32 float4
        int idx = t + i * 256;
        int r = idx >> 5, q = idx & 31;
        int gr = row0 + r;
        float4 v = make_float4(0.f, 0.f, 0.f, 0.f);
        if (gr < N_NODES) v = __ldg(&A4[(size_t)gr * 32 + q]);
        *(float4*)&As[r * SA + q * 4] = v;
    }
#pragma unroll
    for (int i = 0; i < 16; i++) {                    // B: 128 rows x 32 float4
        int idx = t + i * 256;
        int r = idx >> 5, q = idx & 31;
        *(float4*)&Bs[r * SB + q * 4] = __ldg(&B4[idx]);
    }
    __syncthreads();

    float c[8][4];
#pragma unroll
    for (int nt = 0; nt < 8; nt++)
#pragma unroll
        for (int j = 0; j < 4; j++) c[nt][j] = 0.f;

    int lr = lane >> 2, lc = lane & 3;
#pragma unroll
    for (int kk = 0; kk < 16; kk++) {
        int k0 = kk * 8;
        uint32_t a[4], b[8][2];
        int r = warpM * 16 + lr;
        a[0] = Asu[r * SA + k0 + lc];
        a[1] = Asu[(r + 8) * SA + k0 + lc];
        a[2] = Asu[r * SA + k0 + 4 + lc];
        a[3] = Asu[(r + 8) * SA + k0 + 4 + lc];
#pragma unroll
        for (int nt = 0; nt < 8; nt++) {
            int n = warpN * 64 + nt * 8 + lr;
            b[nt][0] = Bsu[(k0 + lc) * SB + n];
            b[nt][1] = Bsu[(k0 + 4 + lc) * SB + n];
        }
#pragma unroll
        for (int nt = 0; nt < 8; nt++)
            mma_tf32(c[nt], a, b[nt]);
    }

    int r0 = row0 + warpM * 16 + lr;
    bool rok0 = (r0 < N_NODES), rok1 = (r0 + 8 < N_NODES);
#pragma unroll
    for (int nt = 0; nt < 8; nt++) {
        int col = warpN * 64 + nt * 8 + lc * 2;
        if (rok0)
            *(float2*)&g_h0[(size_t)r0 * D + col] = make_float2(c[nt][0], c[nt][1]);
        if (rok1)
            *(float2*)&g_h0[(size_t)(r0 + 8) * D + col] = make_float2(c[nt][2], c[nt][3]);
    }
    float* stat = g_stats4 + l * 256;
#pragma unroll
    for (int nt = 0; nt < 8; nt++) {
#pragma unroll
        for (int jj = 0; jj < 2; jj++) {
            float v0 = rok0 ? c[nt][jj] : 0.f;
            float v1 = rok1 ? c[nt][jj + 2] : 0.f;
            float s = v0 + v1;
            float q = v0 * v0 + v1 * v1;
            s += __shfl_down_sync(0xFFFFFFFFu, s, 16);
            q += __shfl_down_sync(0xFFFFFFFFu, q, 16);
            s += __shfl_down_sync(0xFFFFFFFFu, s, 8);
            q += __shfl_down_sync(0xFFFFFFFFu, q, 8);
            s += __shfl_down_sync(0xFFFFFFFFu, s, 4);
            q += __shfl_down_sync(0xFFFFFFFFu, q, 4);
            if (lane < 4) {
                int col = warpN * 64 + nt * 8 + lane * 2 + jj;
                atomicAdd(&stat[col], s);
                atomicAdd(&stat[128 + col], q);
            }
        }
    }
}

// =============== 6. pool: 4-way split per graph, final BN+ReLU, atomic accumulate ==========
__global__ void k_pool(const int* __restrict__ batch, const float* __restrict__ bn_g,
                       const float* __restrict__ bn_b) {
    int g = blockIdx.x, part = blockIdx.y, t = threadIdx.x;   // 128 threads
    int lo = 0, hi = N_NODES;
    while (lo < hi) { int m = (lo + hi) >> 1; if (__ldg(&batch[m]) < g) lo = m + 1; else hi = m; }
    int lo2 = lo, hi2 = N_NODES;
    while (lo2 < hi2) { int m = (lo2 + hi2) >> 1; if (__ldg(&batch[m]) < g + 1) lo2 = m + 1; else hi2 = m; }

    int cnt = lo2 - lo;
    int per = (cnt + 3) >> 2;
    int rs = lo + part * per;
    int re = min(rs + per, lo2);
    if (rs >= re) return;

    float s0 = g_stats4[3 * 256 + t];
    float q0 = g_stats4[3 * 256 + 128 + t];
    float mu = s0 / (float)N_NODES;
    float var = q0 / (float)N_NODES - mu * mu;
    float rstd = rsqrtf(fmaxf(var, 0.f) + BN_EPS);
    float sc = rstd * __ldg(&bn_g[3 * D + t]);
    float sh = __ldg(&bn_b[3 * D + t]) - mu * sc;

    float s = 0.f;
    for (int r = rs; r < re; r++) {
        float v = g_h0[(size_t)r * D + t];
        s += fmaxf(v * sc + sh, 0.f);
    }
    atomicAdd(&g_pool[g * D + t], s);
}

// =============== 7. MLP head (divides pool by count) + g_off re-zero ===============
__global__ void k_mlp(const int* __restrict__ batch,
                      const float* __restrict__ w1, const float* __restrict__ b1,
                      const float* __restrict__ w2, const float* __restrict__ b2,
                      float* __restrict__ out) {
    int g = blockIdx.x, j = threadIdx.x;   // 64 threads
    int lo = 0, hi = N_NODES;
    while (lo < hi) { int m = (lo + hi) >> 1; if (__ldg(&batch[m]) < g) lo = m + 1; else hi = m; }
    int lo2 = lo, hi2 = N_NODES;
    while (lo2 < hi2) { int m = (lo2 + hi2) >> 1; if (__ldg(&batch[m]) < g + 1) lo2 = m + 1; else hi2 = m; }
    float inv = 1.f / (float)max(lo2 - lo, 1);

    const float* gp = g_pool + g * D;
    const float* wr = w1 + j * D;
    float a = b1[j];
#pragma unroll 4
    for (int k = 0; k < D; k++) a += gp[k] * inv * wr[k];
    a = fmaxf(a, 0.f);
    float v = a * w2[j];
#pragma unroll
    for (int o = 16; o > 0; o >>= 1) v += __shfl_down_sync(0xFFFFFFFFu, v, o);
    __shared__ float sh[2];
    if ((j & 31) == 0) sh[j >> 5] = v;
    __syncthreads();
    if (j == 0) out[g] = sh[0] + sh[1] + b2[0];
    // maintain invariant: g_off zeroed for the next kernel_launch call
    for (int i = g * 64 + j; i < N_NODES + 1; i += N_GRAPHS * 64) g_off[i] = 0;
}

// ---------------- launch ----------------
extern "C" void kernel_launch(void* const* d_in, const int* in_sizes, int n_in,
                              void* d_out, int out_size) {
    const int*   x        = (const int*)d_in[0];
    const int*   ei       = (const int*)d_in[1];
    const int*   ea       = (const int*)d_in[2];
    const int*   batch    = (const int*)d_in[3];
    const float* atom_emb = (const float*)d_in[4];
    const float* bond_emb = (const float*)d_in[5];
    const float* lin_w    = (const float*)d_in[6];
    const float* bn_g     = (const float*)d_in[8];
    const float* bn_b     = (const float*)d_in[9];
    const float* w1       = (const float*)d_in[10];
    const float* b1       = (const float*)d_in[11];
    const float* w2       = (const float*)d_in[12];
    const float* b2       = (const float*)d_in[13];
    float* out = (float*)d_out;

    const int* e_src = ei;
    const int* e_dst = ei + N_EDGES;

    cudaFuncSetAttribute(k_gemm, cudaFuncAttributeMaxDynamicSharedMemorySize, GEMM_SMEM);

    k_atomhist<<<(N_NODES * 32 + 255) / 256, 256>>>(x, atom_emb, e_dst);
    k_scanprep<<<1 + CT_BLOCKS + WT_BLOCKS, 1024>>>(bond_emb, lin_w);
    k_scatter<<<(N_TOT + 255) / 256, 256>>>(e_src, e_dst, ea);

    for (int l = 0; l < NLAYER; l++) {
        k_aggr<<<(N_NODES * 32 + 255) / 256, 256>>>(l, bn_g, bn_b);
        k_gemm<<<GEMM_BLOCKS, 256, GEMM_SMEM>>>(l);
    }

    dim3 poolgrid(N_GRAPHS, 4);
    k_pool<<<poolgrid, D>>>(batch, bn_g, bn_b);
    k_mlp<<<N_GRAPHS, 64>>>(batch, w1, b1, w2, b2, out);
}

// round 11
// speedup vs baseline: 1.3507x; 1.3409x over previous
#include <cuda_runtime.h>
#include <cstdint>

#define N_NODES 50000
#define N_EDGES 600000
#define N_TOT   (N_NODES + N_EDGES)
#define N_GRAPHS 256
#define D 128
#define NLAYER 4
#define BN_EPS 1e-5f

// ---------------- scratch (device globals; zero-initialized at load) ----------------
__device__ float g_h0[(size_t)N_NODES * D];      // h buffer (atom emb / z ping)
__device__ float g_h1[(size_t)N_NODES * D];      // aggr buffer
__device__ float g_Wt4[NLAYER * D * D];          // per-layer W^T [k][n], tf32-rounded
__device__ float g_ct4[NLAYER * 243 * D];        // per-layer combo bond-embedding tables
__device__ float g_stats4[NLAYER * 2 * D];       // per-layer col sums + sumsq of z
__device__ float g_pool[N_GRAPHS * D];           // zeroed each call in k_zero
__device__ int   g_off[N_NODES + 1];             // MUST be zero on kernel_launch entry
__device__ int   g_cur[N_NODES];
__device__ int   g_adj[N_TOT];                   // packed: src | (combo<<16)

__device__ __forceinline__ float tf32r(float x) {
    float y;
    asm("cvt.rna.tf32.f32 %0, %1;" : "=f"(y) : "f"(x));
    return y;
}

__device__ __forceinline__ void mma_tf32(float* c, const uint32_t* a, const uint32_t* b) {
    asm volatile(
        "mma.sync.aligned.m16n8k8.row.col.f32.tf32.tf32.f32 "
        "{%0,%1,%2,%3}, {%4,%5,%6,%7}, {%8,%9}, {%0,%1,%2,%3};"
        : "+f"(c[0]), "+f"(c[1]), "+f"(c[2]), "+f"(c[3])
        : "r"(a[0]), "r"(a[1]), "r"(a[2]), "r"(a[3]), "r"(b[0]), "r"(b[1]));
}

// =============== 1. atom embedding + degree histogram + zero stats ===============
__global__ void k_atomhist(const int* __restrict__ x, const float* __restrict__ aemb,
                           const int* __restrict__ e_dst) {
    int gid = blockIdx.x * blockDim.x + threadIdx.x;   // 1.6M threads
    int node = gid >> 5, lane = gid & 31;
    if (node < N_NODES) {
        const int* xi = x + (size_t)node * 9;
        float4 acc = make_float4(0.f, 0.f, 0.f, 0.f);
#pragma unroll
        for (int f = 0; f < 9; f++) {
            int v = __ldg(&xi[f]);
            float4 e = __ldg(&((const float4*)aemb)[(size_t)(f * 120 + v) * 32 + lane]);
            acc.x += e.x; acc.y += e.y; acc.z += e.z; acc.w += e.w;
        }
        ((float4*)g_h0)[(size_t)node * 32 + lane] = acc;
    }
    if (gid < N_EDGES) atomicAdd(&g_off[__ldg(&e_dst[gid])], 1);
    if (gid < NLAYER * 2 * D) g_stats4[gid] = 0.f;
}

// =============== 2. single-block scan (block 0) + all-layer prep (other blocks) ===============
#define CT_BLOCKS ((NLAYER * 243 + 7) / 8)            /* 122 */
#define WT_BLOCKS (NLAYER * D * D / 1024)             /* 64 */
__global__ void k_scanprep(const float* __restrict__ bemb, const float* __restrict__ W) {
    int b = blockIdx.x, t = threadIdx.x;              // 1024 threads
    if (b == 0) {
        __shared__ int sh[1024];
        int base = t * 49;
        int sum = 0;
        for (int i = 0; i < 49; i++) {
            int idx = base + i;
            if (idx < N_NODES) sum += g_off[idx] + 1;  // +1 self loop
        }
        sh[t] = sum;
        __syncthreads();
        for (int off = 1; off < 1024; off <<= 1) {
            int xv = (t >= off) ? sh[t - off] : 0;
            __syncthreads();
            sh[t] += xv;
            __syncthreads();
        }
        int run = sh[t] - sum;                         // exclusive start
        for (int i = 0; i < 49; i++) {
            int idx = base + i;
            if (idx < N_NODES) {
                int c = g_off[idx] + 1;
                g_off[idx] = run;
                g_cur[idx] = run;
                run += c;
            }
        }
        if (t == 1023) g_off[N_NODES] = run;           // == N_TOT
    } else if (b <= CT_BLOCKS) {
        int r = (b - 1) * 8 + (t >> 7);                // 0..971 = l*243 + combo
        int lane = t & 127;
        if (r < NLAYER * 243) {
            int l = r / 243, c = r % 243;
            const float* bl = bemb + (size_t)l * 5 * 7 * D;
            int cc = c;
            float acc = 0.f;
#pragma unroll
            for (int f = 0; f < 5; f++) {
                int dig = cc % 3; cc /= 3;
                acc += __ldg(&bl[(f * 7 + dig) * D + lane]);
            }
            g_ct4[(size_t)r * D + lane] = acc;
        }
    } else {
        int e = (b - 1 - CT_BLOCKS) * 1024 + t;        // 0..65535
        int l = e >> 14, idx = e & 16383;
        int k = idx >> 7, n = idx & 127;
        g_Wt4[e] = tf32r(__ldg(&W[(size_t)l * D * D + n * D + k]));
    }
}

// =============== 3. scatter edges into CSR ===============
__global__ void k_scatter(const int* __restrict__ e_src, const int* __restrict__ e_dst,
                          const int* __restrict__ ea) {
    int t = blockIdx.x * blockDim.x + threadIdx.x;
    if (t >= N_TOT) return;
    int d, s, comb;
    if (t < N_EDGES) {
        s = __ldg(&e_src[t]);
        d = __ldg(&e_dst[t]);
        const int* a = ea + (size_t)t * 5;
        comb = a[0] + 3 * a[1] + 9 * a[2] + 27 * a[3] + 81 * a[4];
    } else {
        d = s = t - N_EDGES;
        comb = 0;
    }
    int pos = atomicAdd(&g_cur[d], 1);
    g_adj[pos] = s | (comb << 16);
}

// =============== 3b. zero g_pool (also shifts profile slot onto gemm0) ===============
__global__ void k_zero() {
    int gid = blockIdx.x * blockDim.x + threadIdx.x;
    if (gid < N_GRAPHS * D) g_pool[gid] = 0.f;
}

// =============== 4. aggregation: warp-per-node, no smem (measured 39.5us, occ 58%) ========
__global__ __launch_bounds__(256) void k_aggr(int l, const float* __restrict__ bn_g,
                                              const float* __restrict__ bn_b) {
    int gid = blockIdx.x * blockDim.x + threadIdx.x;
    int node = gid >> 5, lane = gid & 31;
    if (node >= N_NODES) return;

    float scx, scy, scz, scw, shx, shy, shz, shw, flo;
    if (l > 0) {
        flo = 0.f;
        const float* st = g_stats4 + (l - 1) * 256;
        const float* gg = bn_g + (l - 1) * D;
        const float* bb = bn_b + (l - 1) * D;
        int c0 = lane * 4;
        float sc[4], sh[4];
#pragma unroll
        for (int j = 0; j < 4; j++) {
            float s = __ldg(&st[c0 + j]);
            float q = __ldg(&st[128 + c0 + j]);
            float mu = s * (1.f / (float)N_NODES);
            float var = q * (1.f / (float)N_NODES) - mu * mu;
            float rstd = rsqrtf(fmaxf(var, 0.f) + BN_EPS);
            sc[j] = rstd * __ldg(&gg[c0 + j]);
            sh[j] = __ldg(&bb[c0 + j]) - mu * sc[j];
        }
        scx = sc[0]; scy = sc[1]; scz = sc[2]; scw = sc[3];
        shx = sh[0]; shy = sh[1]; shz = sh[2]; shw = sh[3];
    } else {
        scx = scy = scz = scw = 1.f;
        shx = shy = shz = shw = 0.f;
        flo = __int_as_float(0xff800000);   // -inf: identity on h0
    }

    const float4* h4 = (const float4*)g_h0;
    const float4* ct4 = (const float4*)(g_ct4 + (size_t)l * 243 * D);
    int s = __ldg(&g_off[node]), e = __ldg(&g_off[node + 1]);
    float4 acc = make_float4(0.f, 0.f, 0.f, 0.f);
    int j = s;
    for (; j + 4 <= e; j += 4) {
        int p0 = __ldg(&g_adj[j]);
        int p1 = __ldg(&g_adj[j + 1]);
        int p2 = __ldg(&g_adj[j + 2]);
        int p3 = __ldg(&g_adj[j + 3]);
        float4 z0 = __ldcg(&h4[(size_t)(p0 & 0xFFFF) * 32 + lane]);
        float4 z1 = __ldcg(&h4[(size_t)(p1 & 0xFFFF) * 32 + lane]);
        float4 z2 = __ldcg(&h4[(size_t)(p2 & 0xFFFF) * 32 + lane]);
        float4 z3 = __ldcg(&h4[(size_t)(p3 & 0xFFFF) * 32 + lane]);
        float4 c0 = __ldg(&ct4[(p0 >> 16) * 32 + lane]);
        float4 c1 = __ldg(&ct4[(p1 >> 16) * 32 + lane]);
        float4 c2 = __ldg(&ct4[(p2 >> 16) * 32 + lane]);
        float4 c3 = __ldg(&ct4[(p3 >> 16) * 32 + lane]);
        acc.x += fmaxf(z0.x * scx + shx, flo) + c0.x;
        acc.y += fmaxf(z0.y * scy + shy, flo) + c0.y;
        acc.z += fmaxf(z0.z * scz + shz, flo) + c0.z;
        acc.w += fmaxf(z0.w * scw + shw, flo) + c0.w;
        acc.x += fmaxf(z1.x * scx + shx, flo) + c1.x;
        acc.y += fmaxf(z1.y * scy + shy, flo) + c1.y;
        acc.z += fmaxf(z1.z * scz + shz, flo) + c1.z;
        acc.w += fmaxf(z1.w * scw + shw, flo) + c1.w;
        acc.x += fmaxf(z2.x * scx + shx, flo) + c2.x;
        acc.y += fmaxf(z2.y * scy + shy, flo) + c2.y;
        acc.z += fmaxf(z2.z * scz + shz, flo) + c2.z;
        acc.w += fmaxf(z2.w * scw + shw, flo) + c2.w;
        acc.x += fmaxf(z3.x * scx + shx, flo) + c3.x;
        acc.y += fmaxf(z3.y * scy + shy, flo) + c3.y;
        acc.z += fmaxf(z3.z * scz + shz, flo) + c3.z;
        acc.w += fmaxf(z3.w * scw + shw, flo) + c3.w;
    }
    for (; j < e; j++) {
        int p = __ldg(&g_adj[j]);
        float4 z = __ldcg(&h4[(size_t)(p & 0xFFFF) * 32 + lane]);
        float4 c = __ldg(&ct4[(p >> 16) * 32 + lane]);
        acc.x += fmaxf(z.x * scx + shx, flo) + c.x;
        acc.y += fmaxf(z.y * scy + shy, flo) + c.y;
        acc.z += fmaxf(z.z * scz + shz, flo) + c.z;
        acc.w += fmaxf(z.w * scw + shw, flo) + c.w;
    }
    acc.x = tf32r(acc.x); acc.y = tf32r(acc.y);
    acc.z = tf32r(acc.z); acc.w = tf32r(acc.w);
    ((float4*)g_h1)[(size_t)node * 32 + lane] = acc;
}

// =============== 5. PERSISTENT tf32 mma GEMM: B loaded once, grid-stride A tiles ==========
#define SA 132
#define SB 136
#define AS_FLOATS (64 * SA)
#define BS_FLOATS (128 * SB)
#define GEMM_SMEM ((AS_FLOATS + BS_FLOATS) * 4)    /* ~101KB -> 2 CTAs/SM */
#define N_TILES ((N_NODES + 63) / 64)              /* 782 */
#define PGRID 296                                  /* 2 per SM, single wave */

__global__ __launch_bounds__(256, 2) void k_gemm(int l) {
    extern __shared__ float smem[];
    float* Bs = smem;                                 // [128][136]
    float* As = smem + BS_FLOATS;                     // [64][132]
    const uint32_t* Asu = (const uint32_t*)As;
    const uint32_t* Bsu = (const uint32_t*)Bs;

    int t = threadIdx.x;
    int wid = t >> 5, lane = t & 31;
    int warpM = wid & 3, warpN = wid >> 2;            // 4 x 2 warps
    int lr = lane >> 2, lc = lane & 3;

    // ---- load B once ----
    const float4* B4 = (const float4*)(g_Wt4 + (size_t)l * D * D);
#pragma unroll
    for (int i = 0; i < 16; i++) {
        int idx = t + i * 256;
        int r = idx >> 5, q = idx & 31;
        *(float4*)&Bs[r * SB + q * 4] = __ldg(&B4[idx]);
    }

    // per-thread stats accumulators across tiles (zero-padded rows contribute 0)
    float ts[8][2], tq[8][2];
#pragma unroll
    for (int nt = 0; nt < 8; nt++) { ts[nt][0] = ts[nt][1] = tq[nt][0] = tq[nt][1] = 0.f; }

    const float4* A4 = (const float4*)g_h1;

    for (int tile = blockIdx.x; tile < N_TILES; tile += PGRID) {
        int row0 = tile * 64;
        __syncthreads();   // prior iter's As readers done (also orders B first iter)
#pragma unroll
        for (int i = 0; i < 8; i++) {                 // A: 64 rows x 32 float4
            int idx = t + i * 256;
            int r = idx >> 5, q = idx & 31;
            int gr = row0 + r;
            float4 v = make_float4(0.f, 0.f, 0.f, 0.f);
            if (gr < N_NODES) v = __ldg(&A4[(size_t)gr * 32 + q]);
            *(float4*)&As[r * SA + q * 4] = v;
        }
        __syncthreads();

        float c[8][4];
#pragma unroll
        for (int nt = 0; nt < 8; nt++)
#pragma unroll
            for (int j = 0; j < 4; j++) c[nt][j] = 0.f;

#pragma unroll
        for (int kk = 0; kk < 16; kk++) {
            int k0 = kk * 8;
            uint32_t a[4], b[8][2];
            int r = warpM * 16 + lr;
            a[0] = Asu[r * SA + k0 + lc];
            a[1] = Asu[(r + 8) * SA + k0 + lc];
            a[2] = Asu[r * SA + k0 + 4 + lc];
            a[3] = Asu[(r + 8) * SA + k0 + 4 + lc];
#pragma unroll
            for (int nt = 0; nt < 8; nt++) {
                int n = warpN * 64 + nt * 8 + lr;
                b[nt][0] = Bsu[(k0 + lc) * SB + n];
                b[nt][1] = Bsu[(k0 + 4 + lc) * SB + n];
            }
#pragma unroll
            for (int nt = 0; nt < 8; nt++)
                mma_tf32(c[nt], a, b[nt]);
        }

        int r0 = row0 + warpM * 16 + lr;
        bool rok0 = (r0 < N_NODES), rok1 = (r0 + 8 < N_NODES);
#pragma unroll
        for (int nt = 0; nt < 8; nt++) {
            int col = warpN * 64 + nt * 8 + lc * 2;
            if (rok0)
                *(float2*)&g_h0[(size_t)r0 * D + col] = make_float2(c[nt][0], c[nt][1]);
            if (rok1)
                *(float2*)&g_h0[(size_t)(r0 + 8) * D + col] = make_float2(c[nt][2], c[nt][3]);
#pragma unroll
            for (int jj = 0; jj < 2; jj++) {
                float v0 = c[nt][jj], v1 = c[nt][jj + 2];   // zero rows -> zero contribution
                ts[nt][jj] += v0 + v1;
                tq[nt][jj] += v0 * v0 + v1 * v1;
            }
        }
    }

    // ---- single stats epilogue: shfl over lr, atomics from lanes 0-3 ----
    float* stat = g_stats4 + l * 256;
#pragma unroll
    for (int nt = 0; nt < 8; nt++) {
#pragma unroll
        for (int jj = 0; jj < 2; jj++) {
            float s = ts[nt][jj];
            float q = tq[nt][jj];
            s += __shfl_down_sync(0xFFFFFFFFu, s, 16);
            q += __shfl_down_sync(0xFFFFFFFFu, q, 16);
            s += __shfl_down_sync(0xFFFFFFFFu, s, 8);
            q += __shfl_down_sync(0xFFFFFFFFu, q, 8);
            s += __shfl_down_sync(0xFFFFFFFFu, s, 4);
            q += __shfl_down_sync(0xFFFFFFFFu, q, 4);
            if (lane < 4) {
                int col = warpN * 64 + nt * 8 + lane * 2 + jj;
                atomicAdd(&stat[col], s);
                atomicAdd(&stat[128 + col], q);
            }
        }
    }
}

// =============== 6. pool: 4-way split per graph, final BN+ReLU, atomic accumulate ==========
__global__ void k_pool(const int* __restrict__ batch, const float* __restrict__ bn_g,
                       const float* __restrict__ bn_b) {
    int g = blockIdx.x, part = blockIdx.y, t = threadIdx.x;   // 128 threads
    int lo = 0, hi = N_NODES;
    while (lo < hi) { int m = (lo + hi) >> 1; if (__ldg(&batch[m]) < g) lo = m + 1; else hi = m; }
    int lo2 = lo, hi2 = N_NODES;
    while (lo2 < hi2) { int m = (lo2 + hi2) >> 1; if (__ldg(&batch[m]) < g + 1) lo2 = m + 1; else hi2 = m; }

    int cnt = lo2 - lo;
    int per = (cnt + 3) >> 2;
    int rs = lo + part * per;
    int re = min(rs + per, lo2);
    if (rs >= re) return;

    float s0 = g_stats4[3 * 256 + t];
    float q0 = g_stats4[3 * 256 + 128 + t];
    float mu = s0 / (float)N_NODES;
    float var = q0 / (float)N_NODES - mu * mu;
    float rstd = rsqrtf(fmaxf(var, 0.f) + BN_EPS);
    float sc = rstd * __ldg(&bn_g[3 * D + t]);
    float sh = __ldg(&bn_b[3 * D + t]) - mu * sc;

    float s = 0.f;
    for (int r = rs; r < re; r++) {
        float v = g_h0[(size_t)r * D + t];
        s += fmaxf(v * sc + sh, 0.f);
    }
    atomicAdd(&g_pool[g * D + t], s);
}

// =============== 7. MLP head (divides pool by count) + g_off re-zero ===============
__global__ void k_mlp(const int* __restrict__ batch,
                      const float* __restrict__ w1, const float* __restrict__ b1,
                      const float* __restrict__ w2, const float* __restrict__ b2,
                      float* __restrict__ out) {
    int g = blockIdx.x, j = threadIdx.x;   // 64 threads
    int lo = 0, hi = N_NODES;
    while (lo < hi) { int m = (lo + hi) >> 1; if (__ldg(&batch[m]) < g) lo = m + 1; else hi = m; }
    int lo2 = lo, hi2 = N_NODES;
    while (lo2 < hi2) { int m = (lo2 + hi2) >> 1; if (__ldg(&batch[m]) < g + 1) lo2 = m + 1; else hi2 = m; }
    float inv = 1.f / (float)max(lo2 - lo, 1);

    const float* gp = g_pool + g * D;
    const float* wr = w1 + j * D;
    float a = b1[j];
#pragma unroll 4
    for (int k = 0; k < D; k++) a += gp[k] * inv * wr[k];
    a = fmaxf(a, 0.f);
    float v = a * w2[j];
#pragma unroll
    for (int o = 16; o > 0; o >>= 1) v += __shfl_down_sync(0xFFFFFFFFu, v, o);
    __shared__ float sh[2];
    if ((j & 31) == 0) sh[j >> 5] = v;
    __syncthreads();
    if (j == 0) out[g] = sh[0] + sh[1] + b2[0];
    // maintain invariant: g_off zeroed for the next kernel_launch call
    for (int i = g * 64 + j; i < N_NODES + 1; i += N_GRAPHS * 64) g_off[i] = 0;
}

// ---------------- launch ----------------
extern "C" void kernel_launch(void* const* d_in, const int* in_sizes, int n_in,
                              void* d_out, int out_size) {
    const int*   x        = (const int*)d_in[0];
    const int*   ei       = (const int*)d_in[1];
    const int*   ea       = (const int*)d_in[2];
    const int*   batch    = (const int*)d_in[3];
    const float* atom_emb = (const float*)d_in[4];
    const float* bond_emb = (const float*)d_in[5];
    const float* lin_w    = (const float*)d_in[6];
    const float* bn_g     = (const float*)d_in[8];
    const float* bn_b     = (const float*)d_in[9];
    const float* w1       = (const float*)d_in[10];
    const float* b1       = (const float*)d_in[11];
    const float* w2       = (const float*)d_in[12];
    const float* b2       = (const float*)d_in[13];
    float* out = (float*)d_out;

    const int* e_src = ei;
    const int* e_dst = ei + N_EDGES;

    cudaFuncSetAttribute(k_gemm, cudaFuncAttributeMaxDynamicSharedMemorySize, GEMM_SMEM);

    k_atomhist<<<(N_NODES * 32 + 255) / 256, 256>>>(x, atom_emb, e_dst);   // launch 0
    k_scanprep<<<1 + CT_BLOCKS + WT_BLOCKS, 1024>>>(bond_emb, lin_w);      // launch 1
    k_scatter<<<(N_TOT + 255) / 256, 256>>>(e_src, e_dst, ea);             // launch 2
    k_zero<<<(N_GRAPHS * D + 255) / 256, 256>>>();                         // launch 3

    for (int l = 0; l < NLAYER; l++) {
        k_aggr<<<(N_NODES * 32 + 255) / 256, 256>>>(l, bn_g, bn_b);        // launch 4, 6, 8, 10
        k_gemm<<<PGRID, 256, GEMM_SMEM>>>(l);                              // launch 5 <- PROFILED
    }

    dim3 poolgrid(N_GRAPHS, 4);
    k_pool<<<poolgrid, D>>>(batch, bn_g, bn_b);
    k_mlp<<<N_GRAPHS, 64>>>(batch, w1, b1, w2, b2, out);
}

// round 12
// speedup vs baseline: 1.4103x; 1.0441x over previous
#include <cuda_runtime.h>
#include <cuda_fp16.h>
#include <cstdint>

#define N_NODES 50000
#define N_EDGES 600000
#define N_TOT   (N_NODES + N_EDGES)
#define N_GRAPHS 256
#define D 128
#define NLAYER 4
#define BN_EPS 1e-5f

// ---------------- scratch (device globals; zero-initialized at load) ----------------
__device__ float  g_h0[(size_t)N_NODES * D];      // h buffer fp32 (atom emb / z)
__device__ __half g_h1h[(size_t)N_NODES * D];     // aggregate buffer fp16 (GEMM A)
__device__ __half g_Wh4[NLAYER * D * D];          // per-layer W [n][k] fp16 (B fragment layout)
__device__ float  g_ct4[NLAYER * 243 * D];        // per-layer combo bond-embedding tables
__device__ float  g_stats4[NLAYER * 2 * D];       // per-layer col sums + sumsq of z
__device__ float  g_pool[N_GRAPHS * D];           // zeroed each call in k_atomhist
__device__ int    g_off[N_NODES + 1];             // MUST be zero on kernel_launch entry
__device__ int    g_cur[N_NODES];
__device__ int    g_adj[N_TOT];                   // packed: src | (combo<<16)

__device__ __forceinline__ void mma_f16(float* c, const uint32_t* a, const uint32_t* b) {
    asm volatile(
        "mma.sync.aligned.m16n8k16.row.col.f32.f16.f16.f32 "
        "{%0,%1,%2,%3}, {%4,%5,%6,%7}, {%8,%9}, {%0,%1,%2,%3};"
        : "+f"(c[0]), "+f"(c[1]), "+f"(c[2]), "+f"(c[3])
        : "r"(a[0]), "r"(a[1]), "r"(a[2]), "r"(a[3]), "r"(b[0]), "r"(b[1]));
}

// =============== 1. atom embedding + degree histogram + zero stats/pool ===============
__global__ void k_atomhist(const int* __restrict__ x, const float* __restrict__ aemb,
                           const int* __restrict__ e_dst) {
    int gid = blockIdx.x * blockDim.x + threadIdx.x;   // 1.6M threads
    int node = gid >> 5, lane = gid & 31;
    if (node < N_NODES) {
        const int* xi = x + (size_t)node * 9;
        float4 acc = make_float4(0.f, 0.f, 0.f, 0.f);
#pragma unroll
        for (int f = 0; f < 9; f++) {
            int v = __ldg(&xi[f]);
            float4 e = __ldg(&((const float4*)aemb)[(size_t)(f * 120 + v) * 32 + lane]);
            acc.x += e.x; acc.y += e.y; acc.z += e.z; acc.w += e.w;
        }
        ((float4*)g_h0)[(size_t)node * 32 + lane] = acc;
    }
    if (gid < N_EDGES) atomicAdd(&g_off[__ldg(&e_dst[gid])], 1);
    if (gid < NLAYER * 2 * D) g_stats4[gid] = 0.f;
    if (gid < N_GRAPHS * D) g_pool[gid] = 0.f;
}

// =============== 2. single-block scan (block 0) + all-layer prep (other blocks) ===============
#define CT_BLOCKS ((NLAYER * 243 + 7) / 8)            /* 122 */
#define WT_BLOCKS (NLAYER * D * D / 1024)             /* 64 */
__global__ void k_scanprep(const float* __restrict__ bemb, const float* __restrict__ W) {
    int b = blockIdx.x, t = threadIdx.x;              // 1024 threads
    if (b == 0) {
        __shared__ int sh[1024];
        int base = t * 49;
        int sum = 0;
        for (int i = 0; i < 49; i++) {
            int idx = base + i;
            if (idx < N_NODES) sum += g_off[idx] + 1;  // +1 self loop
        }
        sh[t] = sum;
        __syncthreads();
        for (int off = 1; off < 1024; off <<= 1) {
            int xv = (t >= off) ? sh[t - off] : 0;
            __syncthreads();
            sh[t] += xv;
            __syncthreads();
        }
        int run = sh[t] - sum;                         // exclusive start
        for (int i = 0; i < 49; i++) {
            int idx = base + i;
            if (idx < N_NODES) {
                int c = g_off[idx] + 1;
                g_off[idx] = run;
                g_cur[idx] = run;
                run += c;
            }
        }
        if (t == 1023) g_off[N_NODES] = run;           // == N_TOT
    } else if (b <= CT_BLOCKS) {
        int r = (b - 1) * 8 + (t >> 7);                // 0..971 = l*243 + combo
        int lane = t & 127;
        if (r < NLAYER * 243) {
            int l = r / 243, c = r % 243;
            const float* bl = bemb + (size_t)l * 5 * 7 * D;
            int cc = c;
            float acc = 0.f;
#pragma unroll
            for (int f = 0; f < 5; f++) {
                int dig = cc % 3; cc /= 3;
                acc += __ldg(&bl[(f * 7 + dig) * D + lane]);
            }
            g_ct4[(size_t)r * D + lane] = acc;
        }
    } else {
        int e = (b - 1 - CT_BLOCKS) * 1024 + t;        // 0..65535 — direct [l][n][k] convert
        g_Wh4[e] = __float2half(__ldg(&W[e]));
    }
}

// =============== 3. scatter edges into CSR ===============
__global__ void k_scatter(const int* __restrict__ e_src, const int* __restrict__ e_dst,
                          const int* __restrict__ ea) {
    int t = blockIdx.x * blockDim.x + threadIdx.x;
    if (t >= N_TOT) return;
    int d, s, comb;
    if (t < N_EDGES) {
        s = __ldg(&e_src[t]);
        d = __ldg(&e_dst[t]);
        const int* a = ea + (size_t)t * 5;
        comb = a[0] + 3 * a[1] + 9 * a[2] + 27 * a[3] + 81 * a[4];
    } else {
        d = s = t - N_EDGES;
        comb = 0;
    }
    int pos = atomicAdd(&g_cur[d], 1);
    g_adj[pos] = s | (comb << 16);
}

// =============== 4. aggregation: warp-per-node; writes fp16 aggregates ===============
__global__ __launch_bounds__(256) void k_aggr(int l, const float* __restrict__ bn_g,
                                              const float* __restrict__ bn_b) {
    int gid = blockIdx.x * blockDim.x + threadIdx.x;
    int node = gid >> 5, lane = gid & 31;
    if (node >= N_NODES) return;

    float scx, scy, scz, scw, shx, shy, shz, shw, flo;
    if (l > 0) {
        flo = 0.f;
        const float* st = g_stats4 + (l - 1) * 256;
        const float* gg = bn_g + (l - 1) * D;
        const float* bb = bn_b + (l - 1) * D;
        int c0 = lane * 4;
        float sc[4], sh[4];
#pragma unroll
        for (int j = 0; j < 4; j++) {
            float s = __ldg(&st[c0 + j]);
            float q = __ldg(&st[128 + c0 + j]);
            float mu = s * (1.f / (float)N_NODES);
            float var = q * (1.f / (float)N_NODES) - mu * mu;
            float rstd = rsqrtf(fmaxf(var, 0.f) + BN_EPS);
            sc[j] = rstd * __ldg(&gg[c0 + j]);
            sh[j] = __ldg(&bb[c0 + j]) - mu * sc[j];
        }
        scx = sc[0]; scy = sc[1]; scz = sc[2]; scw = sc[3];
        shx = sh[0]; shy = sh[1]; shz = sh[2]; shw = sh[3];
    } else {
        scx = scy = scz = scw = 1.f;
        shx = shy = shz = shw = 0.f;
        flo = __int_as_float(0xff800000);   // -inf: identity on h0
    }

    const float4* h4 = (const float4*)g_h0;
    const float4* ct4 = (const float4*)(g_ct4 + (size_t)l * 243 * D);
    int s = __ldg(&g_off[node]), e = __ldg(&g_off[node + 1]);
    float4 acc = make_float4(0.f, 0.f, 0.f, 0.f);
    int j = s;
    for (; j + 4 <= e; j += 4) {
        int p0 = __ldg(&g_adj[j]);
        int p1 = __ldg(&g_adj[j + 1]);
        int p2 = __ldg(&g_adj[j + 2]);
        int p3 = __ldg(&g_adj[j + 3]);
        float4 z0 = __ldcg(&h4[(size_t)(p0 & 0xFFFF) * 32 + lane]);
        float4 z1 = __ldcg(&h4[(size_t)(p1 & 0xFFFF) * 32 + lane]);
        float4 z2 = __ldcg(&h4[(size_t)(p2 & 0xFFFF) * 32 + lane]);
        float4 z3 = __ldcg(&h4[(size_t)(p3 & 0xFFFF) * 32 + lane]);
        float4 c0 = __ldg(&ct4[(p0 >> 16) * 32 + lane]);
        float4 c1 = __ldg(&ct4[(p1 >> 16) * 32 + lane]);
        float4 c2 = __ldg(&ct4[(p2 >> 16) * 32 + lane]);
        float4 c3 = __ldg(&ct4[(p3 >> 16) * 32 + lane]);
        acc.x += fmaxf(z0.x * scx + shx, flo) + c0.x;
        acc.y += fmaxf(z0.y * scy + shy, flo) + c0.y;
        acc.z += fmaxf(z0.z * scz + shz, flo) + c0.z;
        acc.w += fmaxf(z0.w * scw + shw, flo) + c0.w;
        acc.x += fmaxf(z1.x * scx + shx, flo) + c1.x;
        acc.y += fmaxf(z1.y * scy + shy, flo) + c1.y;
        acc.z += fmaxf(z1.z * scz + shz, flo) + c1.z;
        acc.w += fmaxf(z1.w * scw + shw, flo) + c1.w;
        acc.x += fmaxf(z2.x * scx + shx, flo) + c2.x;
        acc.y += fmaxf(z2.y * scy + shy, flo) + c2.y;
        acc.z += fmaxf(z2.z * scz + shz, flo) + c2.z;
        acc.w += fmaxf(z2.w * scw + shw, flo) + c2.w;
        acc.x += fmaxf(z3.x * scx + shx, flo) + c3.x;
        acc.y += fmaxf(z3.y * scy + shy, flo) + c3.y;
        acc.z += fmaxf(z3.z * scz + shz, flo) + c3.z;
        acc.w += fmaxf(z3.w * scw + shw, flo) + c3.w;
    }
    for (; j < e; j++) {
        int p = __ldg(&g_adj[j]);
        float4 z = __ldcg(&h4[(size_t)(p & 0xFFFF) * 32 + lane]);
        float4 c = __ldg(&ct4[(p >> 16) * 32 + lane]);
        acc.x += fmaxf(z.x * scx + shx, flo) + c.x;
        acc.y += fmaxf(z.y * scy + shy, flo) + c.y;
        acc.z += fmaxf(z.z * scz + shz, flo) + c.z;
        acc.w += fmaxf(z.w * scw + shw, flo) + c.w;
    }
    // round to fp16 (same 11-bit mantissa as tf32) and store packed
    __half2 lo = __floats2half2_rn(acc.x, acc.y);
    __half2 hi = __floats2half2_rn(acc.z, acc.w);
    uint2 pk = make_uint2(*(uint32_t*)&lo, *(uint32_t*)&hi);
    ((uint2*)g_h1h)[(size_t)node * 32 + lane] = pk;
}

// =============== 5. PERSISTENT fp16 mma GEMM: z = aggr @ W^T, stats fused ===============
#define SAH 136                                    /* A smem stride, halves */
#define SBH 136                                    /* B smem stride, halves */
#define AS_HALVES (64 * SAH)
#define BS_HALVES (128 * SBH)
#define GEMM_SMEM ((AS_HALVES + BS_HALVES) * 2)    /* ~52KB */
#define N_TILES ((N_NODES + 63) / 64)              /* 782 */
#define PGRID 296                                  /* 2 per SM */

__global__ __launch_bounds__(256, 2) void k_gemm(int l) {
    extern __shared__ __half smh[];
    __half* Bh = smh;                                 // [128][136] halves, [n][k]
    __half* Ah = smh + BS_HALVES;                     // [64][136] halves, [m][k]
    const uint32_t* Ahw = (const uint32_t*)Ah;        // word view (2 halves)
    const uint32_t* Bhw = (const uint32_t*)Bh;

    int t = threadIdx.x;
    int wid = t >> 5, lane = t & 31;
    int warpM = wid & 3, warpN = wid >> 2;            // 4 x 2 warps
    int lr = lane >> 2, lc = lane & 3;

    // ---- load B once: W[n][k] fp16, 128x128 halves ----
    const uint4* B4 = (const uint4*)(g_Wh4 + (size_t)l * D * D);
#pragma unroll
    for (int i = 0; i < 8; i++) {
        int idx = t + i * 256;                        // uint4 = 8 halves; 2048 total
        int r = idx >> 4, q = idx & 15;
        *(uint4*)&Bh[r * SBH + q * 8] = __ldg(&B4[idx]);
    }

    float ts[8][2], tq[8][2];
#pragma unroll
    for (int nt = 0; nt < 8; nt++) { ts[nt][0] = ts[nt][1] = tq[nt][0] = tq[nt][1] = 0.f; }

    const uint4* A4 = (const uint4*)g_h1h;

    for (int tile = blockIdx.x; tile < N_TILES; tile += PGRID) {
        int row0 = tile * 64;
        __syncthreads();
#pragma unroll
        for (int i = 0; i < 4; i++) {                 // A: 64 rows x 16 uint4
            int idx = t + i * 256;
            int r = idx >> 4, q = idx & 15;
            int gr = row0 + r;
            uint4 v = make_uint4(0u, 0u, 0u, 0u);
            if (gr < N_NODES) v = __ldg(&A4[(size_t)gr * 16 + q]);
            *(uint4*)&Ah[r * SAH + q * 8] = v;
        }
        __syncthreads();

        float c[8][4];
#pragma unroll
        for (int nt = 0; nt < 8; nt++)
#pragma unroll
            for (int j = 0; j < 4; j++) c[nt][j] = 0.f;

#pragma unroll
        for (int kk = 0; kk < 8; kk++) {              // 8 k-steps of 16
            int kw = kk * 8;                          // k offset in words
            uint32_t a[4], b[8][2];
            int r = warpM * 16 + lr;
            a[0] = Ahw[r * (SAH / 2) + kw + lc];
            a[1] = Ahw[(r + 8) * (SAH / 2) + kw + lc];
            a[2] = Ahw[r * (SAH / 2) + kw + 4 + lc];
            a[3] = Ahw[(r + 8) * (SAH / 2) + kw + 4 + lc];
#pragma unroll
            for (int nt = 0; nt < 8; nt++) {
                int n = warpN * 64 + nt * 8 + lr;
                b[nt][0] = Bhw[n * (SBH / 2) + kw + lc];
                b[nt][1] = Bhw[n * (SBH / 2) + kw + 4 + lc];
            }
#pragma unroll
            for (int nt = 0; nt < 8; nt++)
                mma_f16(c[nt], a, b[nt]);
        }

        int r0 = row0 + warpM * 16 + lr;
        bool rok0 = (r0 < N_NODES), rok1 = (r0 + 8 < N_NODES);
#pragma unroll
        for (int nt = 0; nt < 8; nt++) {
            int col = warpN * 64 + nt * 8 + lc * 2;
            if (rok0)
                *(float2*)&g_h0[(size_t)r0 * D + col] = make_float2(c[nt][0], c[nt][1]);
            if (rok1)
                *(float2*)&g_h0[(size_t)(r0 + 8) * D + col] = make_float2(c[nt][2], c[nt][3]);
#pragma unroll
            for (int jj = 0; jj < 2; jj++) {
                float v0 = c[nt][jj], v1 = c[nt][jj + 2];   // padded rows contribute 0
                ts[nt][jj] += v0 + v1;
                tq[nt][jj] += v0 * v0 + v1 * v1;
            }
        }
    }

    float* stat = g_stats4 + l * 256;
#pragma unroll
    for (int nt = 0; nt < 8; nt++) {
#pragma unroll
        for (int jj = 0; jj < 2; jj++) {
            float s = ts[nt][jj];
            float q = tq[nt][jj];
            s += __shfl_down_sync(0xFFFFFFFFu, s, 16);
            q += __shfl_down_sync(0xFFFFFFFFu, q, 16);
            s += __shfl_down_sync(0xFFFFFFFFu, s, 8);
            q += __shfl_down_sync(0xFFFFFFFFu, q, 8);
            s += __shfl_down_sync(0xFFFFFFFFu, s, 4);
            q += __shfl_down_sync(0xFFFFFFFFu, q, 4);
            if (lane < 4) {
                int col = warpN * 64 + nt * 8 + lane * 2 + jj;
                atomicAdd(&stat[col], s);
                atomicAdd(&stat[128 + col], q);
            }
        }
    }
}

// =============== 6. pool: 4-way split per graph, final BN+ReLU, atomic accumulate ==========
__global__ void k_pool(const int* __restrict__ batch, const float* __restrict__ bn_g,
                       const float* __restrict__ bn_b) {
    int g = blockIdx.x, part = blockIdx.y, t = threadIdx.x;   // 128 threads
    int lo = 0, hi = N_NODES;
    while (lo < hi) { int m = (lo + hi) >> 1; if (__ldg(&batch[m]) < g) lo = m + 1; else hi = m; }
    int lo2 = lo, hi2 = N_NODES;
    while (lo2 < hi2) { int m = (lo2 + hi2) >> 1; if (__ldg(&batch[m]) < g + 1) lo2 = m + 1; else hi2 = m; }

    int cnt = lo2 - lo;
    int per = (cnt + 3) >> 2;
    int rs = lo + part * per;
    int re = min(rs + per, lo2);
    if (rs >= re) return;

    float s0 = g_stats4[3 * 256 + t];
    float q0 = g_stats4[3 * 256 + 128 + t];
    float mu = s0 / (float)N_NODES;
    float var = q0 / (float)N_NODES - mu * mu;
    float rstd = rsqrtf(fmaxf(var, 0.f) + BN_EPS);
    float sc = rstd * __ldg(&bn_g[3 * D + t]);
    float sh = __ldg(&bn_b[3 * D + t]) - mu * sc;

    float s = 0.f;
    for (int r = rs; r < re; r++) {
        float v = g_h0[(size_t)r * D + t];
        s += fmaxf(v * sc + sh, 0.f);
    }
    atomicAdd(&g_pool[g * D + t], s);
}

// =============== 7. MLP head (divides pool by count) + g_off re-zero ===============
__global__ void k_mlp(const int* __restrict__ batch,
                      const float* __restrict__ w1, const float* __restrict__ b1,
                      const float* __restrict__ w2, const float* __restrict__ b2,
                      float* __restrict__ out) {
    int g = blockIdx.x, j = threadIdx.x;   // 64 threads
    int lo = 0, hi = N_NODES;
    while (lo < hi) { int m = (lo + hi) >> 1; if (__ldg(&batch[m]) < g) lo = m + 1; else hi = m; }
    int lo2 = lo, hi2 = N_NODES;
    while (lo2 < hi2) { int m = (lo2 + hi2) >> 1; if (__ldg(&batch[m]) < g + 1) lo2 = m + 1; else hi2 = m; }
    float inv = 1.f / (float)max(lo2 - lo, 1);

    const float* gp = g_pool + g * D;
    const float* wr = w1 + j * D;
    float a = b1[j];
#pragma unroll 4
    for (int k = 0; k < D; k++) a += gp[k] * inv * wr[k];
    a = fmaxf(a, 0.f);
    float v = a * w2[j];
#pragma unroll
    for (int o = 16; o > 0; o >>= 1) v += __shfl_down_sync(0xFFFFFFFFu, v, o);
    __shared__ float sh[2];
    if ((j & 31) == 0) sh[j >> 5] = v;
    __syncthreads();
    if (j == 0) out[g] = sh[0] + sh[1] + b2[0];
    // maintain invariant: g_off zeroed for the next kernel_launch call
    for (int i = g * 64 + j; i < N_NODES + 1; i += N_GRAPHS * 64) g_off[i] = 0;
}

// ---------------- launch ----------------
extern "C" void kernel_launch(void* const* d_in, const int* in_sizes, int n_in,
                              void* d_out, int out_size) {
    const int*   x        = (const int*)d_in[0];
    const int*   ei       = (const int*)d_in[1];
    const int*   ea       = (const int*)d_in[2];
    const int*   batch    = (const int*)d_in[3];
    const float* atom_emb = (const float*)d_in[4];
    const float* bond_emb = (const float*)d_in[5];
    const float* lin_w    = (const float*)d_in[6];
    const float* bn_g     = (const float*)d_in[8];
    const float* bn_b     = (const float*)d_in[9];
    const float* w1       = (const float*)d_in[10];
    const float* b1       = (const float*)d_in[11];
    const float* w2       = (const float*)d_in[12];
    const float* b2       = (const float*)d_in[13];
    float* out = (float*)d_out;

    const int* e_src = ei;
    const int* e_dst = ei + N_EDGES;

    cudaFuncSetAttribute(k_gemm, cudaFuncAttributeMaxDynamicSharedMemorySize, GEMM_SMEM);

    k_atomhist<<<(N_NODES * 32 + 255) / 256, 256>>>(x, atom_emb, e_dst);   // 0
    k_scanprep<<<1 + CT_BLOCKS + WT_BLOCKS, 1024>>>(bond_emb, lin_w);      // 1
    k_scatter<<<(N_TOT + 255) / 256, 256>>>(e_src, e_dst, ea);             // 2

    for (int l = 0; l < NLAYER; l++) {
        k_aggr<<<(N_NODES * 32 + 255) / 256, 256>>>(l, bn_g, bn_b);        // 3 <- profiled
        k_gemm<<<PGRID, 256, GEMM_SMEM>>>(l);
    }

    dim3 poolgrid(N_GRAPHS, 4);
    k_pool<<<poolgrid, D>>>(batch, bn_g, bn_b);
    k_mlp<<<N_GRAPHS, 64>>>(batch, w1, b1, w2, b2, out);
}